// round 11
// baseline (speedup 1.0000x reference)
#include <cuda_runtime.h>
#include <cuda_fp16.h>
#include <cstdint>

// ---------------- Problem dims ----------------
static constexpr int T   = 20;
static constexpr int B   = 1024;
static constexpr int IN  = 2048;
static constexpr int OUT = 2048;
static constexpr int M   = T * B;          // 20480
static constexpr int K   = IN;             // 2048
static constexpr int N   = OUT;            // 2048

// GEMM tiling: 128x128x64, 256 threads, 2 CTAs/SM, 2 stages, SW128 swizzle (no pad)
static constexpr int BM = 128;
static constexpr int BN = 128;
static constexpr int BK = 64;              // 64 halfs = 128B row
static constexpr int NCHUNK = K / BK;      // 32

static constexpr int TILE_B  = 128 * 128;          // 16384 B per matrix tile
static constexpr int STAGE_B = 3 * TILE_B;         // A + Bhi + Blo = 49152
static constexpr int SMEM_B  = 2 * STAGE_B;        // 98304 (2 CTAs/SM -> 192KB)

// ---------------- scratch (no cudaMalloc allowed) ----------------
__device__ __half g_xh [(size_t)M * K];    // 84 MB  x in fp16 (exact: x is 0/1)
__device__ __half g_whi[(size_t)N * K];    // 8 MB   weight hi (fp16)
__device__ __half g_wlo[(size_t)N * K];    // 8 MB   weight lo (fp16 residual)
__device__ float  g_cur[(size_t)M * N];    // 168 MB GEMM result (fp32)

// ---------------- helpers ----------------
__device__ __forceinline__ uint32_t smem_u32(const void* p) {
    uint32_t a;
    asm("{ .reg .u64 t; cvta.to.shared.u64 t, %1; cvt.u32.u64 %0, t; }" : "=r"(a) : "l"(p));
    return a;
}
__device__ __forceinline__ void cp16(uint32_t dst, const void* src) {
    asm volatile("cp.async.cg.shared.global [%0], [%1], 16;\n" :: "r"(dst), "l"(src));
}
__device__ __forceinline__ void ldm_x4(uint32_t* r, uint32_t addr) {
    asm volatile("ldmatrix.sync.aligned.m8n8.x4.shared.b16 {%0,%1,%2,%3}, [%4];"
                 : "=r"(r[0]), "=r"(r[1]), "=r"(r[2]), "=r"(r[3]) : "r"(addr));
}
// hi: f32 accumulator
__device__ __forceinline__ void mma16816_f32(float* d, const uint32_t* a, uint32_t b0, uint32_t b1) {
    asm volatile(
        "mma.sync.aligned.m16n8k16.row.col.f32.f16.f16.f32 "
        "{%0,%1,%2,%3}, {%4,%5,%6,%7}, {%8,%9}, {%0,%1,%2,%3};"
        : "+f"(d[0]), "+f"(d[1]), "+f"(d[2]), "+f"(d[3])
        : "r"(a[0]), "r"(a[1]), "r"(a[2]), "r"(a[3]), "r"(b0), "r"(b1));
}
// lo: f16 accumulator (2 regs = 4 halves, same (row,col) mapping as f32 variant)
__device__ __forceinline__ void mma16816_f16(uint32_t* d, const uint32_t* a, uint32_t b0, uint32_t b1) {
    asm volatile(
        "mma.sync.aligned.m16n8k16.row.col.f16.f16.f16.f16 "
        "{%0,%1}, {%2,%3,%4,%5}, {%6,%7}, {%0,%1};"
        : "+r"(d[0]), "+r"(d[1])
        : "r"(a[0]), "r"(a[1]), "r"(a[2]), "r"(a[3]), "r"(b0), "r"(b1));
}
__device__ __forceinline__ uint32_t sw128(uint32_t off) {
    return off ^ ((off >> 3) & 0x70);
}

// ---------------- prep kernels ----------------
__global__ void split_w_kernel(const float* __restrict__ w) {
    int i = blockIdx.x * blockDim.x + threadIdx.x;
    if (i < N * K) {
        float v = w[i];
        __half hi = __float2half_rn(v);
        float r = v - __half2float(hi);
        g_whi[i] = hi;
        g_wlo[i] = __float2half_rn(r);
    }
}

__global__ void conv_x_kernel(const float* __restrict__ x) {
    size_t i = (size_t)blockIdx.x * blockDim.x + threadIdx.x;
    if (i < ((size_t)M * K) / 4) {
        float4 v = reinterpret_cast<const float4*>(x)[i];
        __half2 h0 = __floats2half2_rn(v.x, v.y);
        __half2 h1 = __floats2half2_rn(v.z, v.w);
        uint2 packed;
        packed.x = *reinterpret_cast<uint32_t*>(&h0);
        packed.y = *reinterpret_cast<uint32_t*>(&h1);
        reinterpret_cast<uint2*>(g_xh)[i] = packed;
    }
}

// ---------------- GEMM: hi f32-acc + lo f16-acc, 2 CTAs/SM ----------------
__global__ void __launch_bounds__(256, 2) gemm_kernel() {
    extern __shared__ char smem[];
    const uint32_t sb = smem_u32(smem);
    const int tid = threadIdx.x;
    const int lid = tid & 31;
    const int wid = tid >> 5;

    const int m0 = blockIdx.y * BM;
    const int n0 = blockIdx.x * BN;

    // warp layout: 2 (m) x 4 (n), warp tile 64x32
    const int wm = (wid & 1) * 64;
    const int wn = (wid >> 1) * 32;

    const int a_row = wm + (lid & 15);
    const int a_kb  = (lid >> 4) << 4;
    const int b_row = wn + (lid & 7) + ((lid >> 4) << 3);
    const int b_kb  = ((lid >> 3) & 1) << 4;

    auto issue = [&](int c) {
        if (c < NCHUNK) {
            const int k0 = c * BK;
            const uint32_t base = sb + (c & 1) * STAGE_B;
            #pragma unroll
            for (int i = 0; i < 4; i++) {
                int id = tid + i * 256;
                int row = id >> 3, kc = id & 7;
                uint32_t soff = sw128((uint32_t)(row * 128 + kc * 16));
                const size_t gco = k0 + kc * 8;
                cp16(base + soff,              g_xh  + (size_t)(m0 + row) * K + gco);
                cp16(base + TILE_B + soff,     g_whi + (size_t)(n0 + row) * K + gco);
                cp16(base + 2 * TILE_B + soff, g_wlo + (size_t)(n0 + row) * K + gco);
            }
        }
        asm volatile("cp.async.commit_group;\n" ::: "memory");
    };

    issue(0);

    float acc[4][4][4];
    uint32_t accl[4][4][2];
    #pragma unroll
    for (int i = 0; i < 4; i++)
        #pragma unroll
        for (int j = 0; j < 4; j++) {
            #pragma unroll
            for (int r = 0; r < 4; r++) acc[i][j][r] = 0.0f;
            accl[i][j][0] = 0u; accl[i][j][1] = 0u;
        }

    #pragma unroll 1
    for (int c = 0; c < NCHUNK; c++) {
        asm volatile("cp.async.wait_group 0;\n" ::: "memory");
        __syncthreads();
        issue(c + 1);

        const uint32_t sA  = sb + (c & 1) * STAGE_B;
        const uint32_t sBh = sA + TILE_B;
        const uint32_t sBl = sA + 2 * TILE_B;

        #pragma unroll
        for (int ks = 0; ks < 4; ks++) {
            uint32_t a[4][4];
            #pragma unroll
            for (int mi = 0; mi < 4; mi++) {
                uint32_t off = sw128((uint32_t)((a_row + mi * 16) * 128 + ks * 32 + a_kb));
                ldm_x4(a[mi], sA + off);
            }
            #pragma unroll
            for (int bi = 0; bi < 2; bi++) {
                uint32_t off = sw128((uint32_t)((b_row + bi * 16) * 128 + ks * 32 + b_kb));
                uint32_t bh[4], bl[4];
                ldm_x4(bh, sBh + off);
                ldm_x4(bl, sBl + off);
                #pragma unroll
                for (int mi = 0; mi < 4; mi++) {
                    #pragma unroll
                    for (int njj = 0; njj < 2; njj++) {
                        const int nj = bi * 2 + njj, pr = njj * 2;
                        mma16816_f32(acc[mi][nj], a[mi], bh[pr], bh[pr + 1]);
                        mma16816_f16(accl[mi][nj], a[mi], bl[pr], bl[pr + 1]);
                    }
                }
            }
        }
        __syncthreads();
    }

    // epilogue: fold lo (f16) into hi (f32), store
    const int r_base = m0 + wm + (lid >> 2);
    const int c_base = n0 + wn + (lid & 3) * 2;
    #pragma unroll
    for (int mi = 0; mi < 4; mi++) {
        #pragma unroll
        for (int nj = 0; nj < 4; nj++) {
            __half2 l01 = *reinterpret_cast<__half2*>(&accl[mi][nj][0]);
            __half2 l23 = *reinterpret_cast<__half2*>(&accl[mi][nj][1]);
            float2 f01 = __half22float2(l01);
            float2 f23 = __half22float2(l23);
            float2 v01 = make_float2(acc[mi][nj][0] + f01.x, acc[mi][nj][1] + f01.y);
            float2 v23 = make_float2(acc[mi][nj][2] + f23.x, acc[mi][nj][3] + f23.y);
            *reinterpret_cast<float2*>(
                &g_cur[(size_t)(r_base + mi * 16) * N + c_base + nj * 8]) = v01;
            *reinterpret_cast<float2*>(
                &g_cur[(size_t)(r_base + mi * 16 + 8) * N + c_base + nj * 8]) = v23;
        }
    }
}

// ---------------- LIF scan kernel ----------------
__global__ void scan_kernel(float* __restrict__ out) {
    const int id = blockIdx.x * blockDim.x + threadIdx.x;
    const int o = id & (N - 1);
    const int b = id >> 11;
    const float alpha_s = 0.8f;
    const float alpha_m = 0.95f;
    const float inv_tau = 0.05f;
    float V = 0.0f, I = 0.0f;
    #pragma unroll
    for (int t = 0; t < T; t++) {
        const size_t idx = ((size_t)(t * B + b)) * N + o;
        float cu = g_cur[idx];
        I = alpha_s * I + cu;
        V = alpha_m * V + inv_tau * I;
        float s = (V >= 1.0f) ? 1.0f : 0.0f;
        out[idx] = s;
        V = (V >= 1.0f) ? 0.0f : V;
    }
}

// ---------------- launch ----------------
extern "C" void kernel_launch(void* const* d_in, const int* in_sizes, int n_in,
                              void* d_out, int out_size) {
    const float* x = (const float*)d_in[0];       // [T, B, IN] fp32, binary
    const float* w = (const float*)d_in[1];       // [OUT, IN]  fp32
    float* out = (float*)d_out;                   // [T, B, OUT] fp32

    cudaFuncSetAttribute(gemm_kernel, cudaFuncAttributeMaxDynamicSharedMemorySize, SMEM_B);

    split_w_kernel<<<(N * K + 255) / 256, 256>>>(w);
    conv_x_kernel<<<(int)(((size_t)M * K / 4 + 255) / 256), 256>>>(x);
    gemm_kernel<<<dim3(N / BN, M / BM), 256, SMEM_B>>>();
    scan_kernel<<<(B * N) / 256, 256>>>(out);
}

// round 12
// speedup vs baseline: 1.0415x; 1.0415x over previous
#include <cuda_runtime.h>
#include <cuda_fp16.h>
#include <cstdint>

// ---------------- Problem dims ----------------
static constexpr int T   = 20;
static constexpr int B   = 1024;
static constexpr int IN  = 2048;
static constexpr int OUT = 2048;
static constexpr int M   = T * B;          // 20480
static constexpr int K   = IN;             // 2048
static constexpr int N   = OUT;            // 2048

// GEMM tiling: 128x128x64, 256 threads, 2 CTAs/SM, 2 stages, SW128 swizzle (no pad)
static constexpr int BM = 128;
static constexpr int BN = 128;
static constexpr int BK = 64;              // 64 halfs = 128B row
static constexpr int NCHUNK = K / BK;      // 32

static constexpr int TILE_B  = 128 * 128;          // 16384 B per matrix tile
static constexpr int STAGE_B = 3 * TILE_B;         // A + Bhi + Blo = 49152
static constexpr int SMEM_B  = 2 * STAGE_B;        // 98304 (2 CTAs/SM -> 192KB)

// ---------------- scratch (no cudaMalloc allowed) ----------------
__device__ __half g_xh [(size_t)M * K];    // 84 MB  x in fp16 (exact: x is 0/1)
__device__ __half g_whi[(size_t)N * K];    // 8 MB   weight hi (fp16)
__device__ __half g_wlo[(size_t)N * K];    // 8 MB   weight lo (fp16 residual)
__device__ float  g_cur[(size_t)M * N];    // 168 MB GEMM result (fp32)

// ---------------- helpers ----------------
__device__ __forceinline__ uint32_t smem_u32(const void* p) {
    uint32_t a;
    asm("{ .reg .u64 t; cvta.to.shared.u64 t, %1; cvt.u32.u64 %0, t; }" : "=r"(a) : "l"(p));
    return a;
}
__device__ __forceinline__ void cp16(uint32_t dst, const void* src) {
    asm volatile("cp.async.cg.shared.global [%0], [%1], 16;\n" :: "r"(dst), "l"(src));
}
__device__ __forceinline__ void ldm_x4(uint32_t* r, uint32_t addr) {
    asm volatile("ldmatrix.sync.aligned.m8n8.x4.shared.b16 {%0,%1,%2,%3}, [%4];"
                 : "=r"(r[0]), "=r"(r[1]), "=r"(r[2]), "=r"(r[3]) : "r"(addr));
}
__device__ __forceinline__ void mma16816(float* d, const uint32_t* a, uint32_t b0, uint32_t b1) {
    asm volatile(
        "mma.sync.aligned.m16n8k16.row.col.f32.f16.f16.f32 "
        "{%0,%1,%2,%3}, {%4,%5,%6,%7}, {%8,%9}, {%0,%1,%2,%3};"
        : "+f"(d[0]), "+f"(d[1]), "+f"(d[2]), "+f"(d[3])
        : "r"(a[0]), "r"(a[1]), "r"(a[2]), "r"(a[3]), "r"(b0), "r"(b1));
}
__device__ __forceinline__ uint32_t sw128(uint32_t off) {
    return off ^ ((off >> 3) & 0x70);
}
// streaming (evict-first) 8B store
__device__ __forceinline__ void stg_cs_f2(float* p, float2 v) {
    asm volatile("st.global.cs.v2.f32 [%0], {%1, %2};" :: "l"(p), "f"(v.x), "f"(v.y) : "memory");
}

// ---------------- prep kernels ----------------
__global__ void split_w_kernel(const float* __restrict__ w) {
    int i = blockIdx.x * blockDim.x + threadIdx.x;
    if (i < N * K) {
        float v = w[i];
        __half hi = __float2half_rn(v);
        float r = v - __half2float(hi);
        g_whi[i] = hi;
        g_wlo[i] = __float2half_rn(r);
    }
}

__global__ void conv_x_kernel(const float* __restrict__ x) {
    size_t i = (size_t)blockIdx.x * blockDim.x + threadIdx.x;
    if (i < ((size_t)M * K) / 4) {
        // single-use stream: evict-first on both sides
        float4 v = __ldcs(&reinterpret_cast<const float4*>(x)[i]);
        __half2 h0 = __floats2half2_rn(v.x, v.y);
        __half2 h1 = __floats2half2_rn(v.z, v.w);
        uint2 packed;
        packed.x = *reinterpret_cast<uint32_t*>(&h0);
        packed.y = *reinterpret_cast<uint32_t*>(&h1);
        __stcs(&reinterpret_cast<uint2*>(g_xh)[i], packed);
    }
}

// ---------------- GEMM: 128x128x64, 256 thr, 2 CTAs/SM, fp16 2-split mma.sync ----------------
__global__ void __launch_bounds__(256, 2) gemm_kernel() {
    extern __shared__ char smem[];
    const uint32_t sb = smem_u32(smem);
    const int tid = threadIdx.x;
    const int lid = tid & 31;
    const int wid = tid >> 5;

    const int m0 = blockIdx.y * BM;
    const int n0 = blockIdx.x * BN;

    // warp layout: 2 (m) x 4 (n), warp tile 64x32
    const int wm = (wid & 1) * 64;
    const int wn = (wid >> 1) * 32;

    const int a_row = wm + (lid & 15);
    const int a_kb  = (lid >> 4) << 4;
    const int b_row = wn + (lid & 7) + ((lid >> 4) << 3);
    const int b_kb  = ((lid >> 3) & 1) << 4;

    auto issue = [&](int c) {
        if (c < NCHUNK) {
            const int k0 = c * BK;
            const uint32_t base = sb + (c & 1) * STAGE_B;
            #pragma unroll
            for (int i = 0; i < 4; i++) {
                int id = tid + i * 256;
                int row = id >> 3, kc = id & 7;
                uint32_t soff = sw128((uint32_t)(row * 128 + kc * 16));
                const size_t gco = k0 + kc * 8;
                cp16(base + soff,              g_xh  + (size_t)(m0 + row) * K + gco);
                cp16(base + TILE_B + soff,     g_whi + (size_t)(n0 + row) * K + gco);
                cp16(base + 2 * TILE_B + soff, g_wlo + (size_t)(n0 + row) * K + gco);
            }
        }
        asm volatile("cp.async.commit_group;\n" ::: "memory");
    };

    issue(0);

    float acc[4][4][4];
    #pragma unroll
    for (int i = 0; i < 4; i++)
        #pragma unroll
        for (int j = 0; j < 4; j++)
            #pragma unroll
            for (int r = 0; r < 4; r++) acc[i][j][r] = 0.0f;

    #pragma unroll 1
    for (int c = 0; c < NCHUNK; c++) {
        asm volatile("cp.async.wait_group 0;\n" ::: "memory");
        __syncthreads();
        issue(c + 1);

        const uint32_t sA  = sb + (c & 1) * STAGE_B;
        const uint32_t sBh = sA + TILE_B;
        const uint32_t sBl = sA + 2 * TILE_B;

        #pragma unroll
        for (int ks = 0; ks < 4; ks++) {
            uint32_t a[4][4];
            #pragma unroll
            for (int mi = 0; mi < 4; mi++) {
                uint32_t off = sw128((uint32_t)((a_row + mi * 16) * 128 + ks * 32 + a_kb));
                ldm_x4(a[mi], sA + off);
            }
            #pragma unroll
            for (int bi = 0; bi < 2; bi++) {
                uint32_t off = sw128((uint32_t)((b_row + bi * 16) * 128 + ks * 32 + b_kb));
                uint32_t bh[4], bl[4];
                ldm_x4(bh, sBh + off);
                ldm_x4(bl, sBl + off);
                #pragma unroll
                for (int mi = 0; mi < 4; mi++) {
                    #pragma unroll
                    for (int njj = 0; njj < 2; njj++) {
                        const int nj = bi * 2 + njj, pr = njj * 2;
                        mma16816(acc[mi][nj], a[mi], bh[pr], bh[pr + 1]);
                        mma16816(acc[mi][nj], a[mi], bl[pr], bl[pr + 1]);
                    }
                }
            }
        }
        __syncthreads();
    }

    // epilogue: streaming stores (g_cur is single-use until scan; keep W/A hot in L2)
    const int r_base = m0 + wm + (lid >> 2);
    const int c_base = n0 + wn + (lid & 3) * 2;
    #pragma unroll
    for (int mi = 0; mi < 4; mi++) {
        #pragma unroll
        for (int nj = 0; nj < 4; nj++) {
            stg_cs_f2(&g_cur[(size_t)(r_base + mi * 16) * N + c_base + nj * 8],
                      make_float2(acc[mi][nj][0], acc[mi][nj][1]));
            stg_cs_f2(&g_cur[(size_t)(r_base + mi * 16 + 8) * N + c_base + nj * 8],
                      make_float2(acc[mi][nj][2], acc[mi][nj][3]));
        }
    }
}

// ---------------- LIF scan kernel ----------------
__global__ void scan_kernel(float* __restrict__ out) {
    const int id = blockIdx.x * blockDim.x + threadIdx.x;
    const int o = id & (N - 1);
    const int b = id >> 11;
    const float alpha_s = 0.8f;
    const float alpha_m = 0.95f;
    const float inv_tau = 0.05f;
    float V = 0.0f, I = 0.0f;
    #pragma unroll
    for (int t = 0; t < T; t++) {
        const size_t idx = ((size_t)(t * B + b)) * N + o;
        float cu = __ldcs(&g_cur[idx]);          // single-use stream
        I = alpha_s * I + cu;
        V = alpha_m * V + inv_tau * I;
        float s = (V >= 1.0f) ? 1.0f : 0.0f;
        __stcs(&out[idx], s);
        V = (V >= 1.0f) ? 0.0f : V;
    }
}

// ---------------- launch ----------------
extern "C" void kernel_launch(void* const* d_in, const int* in_sizes, int n_in,
                              void* d_out, int out_size) {
    const float* x = (const float*)d_in[0];       // [T, B, IN] fp32, binary
    const float* w = (const float*)d_in[1];       // [OUT, IN]  fp32
    float* out = (float*)d_out;                   // [T, B, OUT] fp32

    cudaFuncSetAttribute(gemm_kernel, cudaFuncAttributeMaxDynamicSharedMemorySize, SMEM_B);

    // conv_x first (streams 504MB with .cs), split_w last so W digits are L2-hot for GEMM
    conv_x_kernel<<<(int)(((size_t)M * K / 4 + 255) / 256), 256>>>(x);
    split_w_kernel<<<(N * K + 255) / 256, 256>>>(w);
    gemm_kernel<<<dim3(N / BN, M / BM), 256, SMEM_B>>>();
    scan_kernel<<<(B * N) / 256, 256>>>(out);
}

// round 13
// speedup vs baseline: 1.0836x; 1.0404x over previous
#include <cuda_runtime.h>
#include <cuda_fp16.h>
#include <cstdint>

// ---------------- Problem dims ----------------
static constexpr int T   = 20;
static constexpr int B   = 1024;
static constexpr int IN  = 2048;
static constexpr int OUT = 2048;
static constexpr int M   = T * B;          // 20480
static constexpr int K   = IN;             // 2048
static constexpr int N   = OUT;            // 2048

// GEMM tiling: 128x128x64, 256 threads, 2 CTAs/SM, 2 stages, SW128 swizzle (no pad)
static constexpr int BM = 128;
static constexpr int BN = 128;
static constexpr int BK = 64;              // 64 halfs = 128B row
static constexpr int NCHUNK = K / BK;      // 32

static constexpr int TILE_B  = 128 * 128;          // 16384 B per matrix tile
static constexpr int STAGE_B = 3 * TILE_B;         // A + Bhi + Blo = 49152
static constexpr int SMEM_B  = 2 * STAGE_B;        // 98304 (2 CTAs/SM -> 192KB)

// ---------------- scratch (no cudaMalloc allowed) ----------------
__device__ __half g_xh [(size_t)M * K];    // 84 MB  x in fp16 (exact: x is 0/1)
__device__ __half g_whi[(size_t)N * K];    // 8 MB   weight hi (fp16)
__device__ __half g_wlo[(size_t)N * K];    // 8 MB   weight lo (fp16 residual)
__device__ float  g_cur[(size_t)M * N];    // 168 MB GEMM result (fp32)

// ---------------- helpers ----------------
__device__ __forceinline__ uint32_t smem_u32(const void* p) {
    uint32_t a;
    asm("{ .reg .u64 t; cvta.to.shared.u64 t, %1; cvt.u32.u64 %0, t; }" : "=r"(a) : "l"(p));
    return a;
}
__device__ __forceinline__ void cp16(uint32_t dst, const void* src) {
    asm volatile("cp.async.cg.shared.global [%0], [%1], 16;\n" :: "r"(dst), "l"(src));
}
__device__ __forceinline__ void ldm_x4(uint32_t* r, uint32_t addr) {
    asm volatile("ldmatrix.sync.aligned.m8n8.x4.shared.b16 {%0,%1,%2,%3}, [%4];"
                 : "=r"(r[0]), "=r"(r[1]), "=r"(r[2]), "=r"(r[3]) : "r"(addr));
}
__device__ __forceinline__ void mma16816(float* d, const uint32_t* a, uint32_t b0, uint32_t b1) {
    asm volatile(
        "mma.sync.aligned.m16n8k16.row.col.f32.f16.f16.f32 "
        "{%0,%1,%2,%3}, {%4,%5,%6,%7}, {%8,%9}, {%0,%1,%2,%3};"
        : "+f"(d[0]), "+f"(d[1]), "+f"(d[2]), "+f"(d[3])
        : "r"(a[0]), "r"(a[1]), "r"(a[2]), "r"(a[3]), "r"(b0), "r"(b1));
}
__device__ __forceinline__ uint32_t sw128(uint32_t off) {
    return off ^ ((off >> 3) & 0x70);
}
// streaming (evict-first) 8B store — kept for GEMM epilogue only
__device__ __forceinline__ void stg_cs_f2(float* p, float2 v) {
    asm volatile("st.global.cs.v2.f32 [%0], {%1, %2};" :: "l"(p), "f"(v.x), "f"(v.y) : "memory");
}

// ---------------- prep kernels ----------------
__global__ void split_w_kernel(const float* __restrict__ w) {
    int i = blockIdx.x * blockDim.x + threadIdx.x;
    if (i < N * K) {
        float v = w[i];
        __half hi = __float2half_rn(v);
        float r = v - __half2float(hi);
        g_whi[i] = hi;
        g_wlo[i] = __float2half_rn(r);
    }
}

__global__ void conv_x_kernel(const float* __restrict__ x) {
    size_t i = (size_t)blockIdx.x * blockDim.x + threadIdx.x;
    if (i < ((size_t)M * K) / 4) {
        // single-use stream: evict-first on both sides (helped in R12)
        float4 v = __ldcs(&reinterpret_cast<const float4*>(x)[i]);
        __half2 h0 = __floats2half2_rn(v.x, v.y);
        __half2 h1 = __floats2half2_rn(v.z, v.w);
        uint2 packed;
        packed.x = *reinterpret_cast<uint32_t*>(&h0);
        packed.y = *reinterpret_cast<uint32_t*>(&h1);
        __stcs(&reinterpret_cast<uint2*>(g_xh)[i], packed);
    }
}

// ---------------- GEMM: 128x128x64, 256 thr, 2 CTAs/SM, fp16 2-split mma.sync ----------------
__global__ void __launch_bounds__(256, 2) gemm_kernel() {
    extern __shared__ char smem[];
    const uint32_t sb = smem_u32(smem);
    const int tid = threadIdx.x;
    const int lid = tid & 31;
    const int wid = tid >> 5;

    const int m0 = blockIdx.y * BM;
    const int n0 = blockIdx.x * BN;

    // warp layout: 2 (m) x 4 (n), warp tile 64x32
    const int wm = (wid & 1) * 64;
    const int wn = (wid >> 1) * 32;

    const int a_row = wm + (lid & 15);
    const int a_kb  = (lid >> 4) << 4;
    const int b_row = wn + (lid & 7) + ((lid >> 4) << 3);
    const int b_kb  = ((lid >> 3) & 1) << 4;

    auto issue = [&](int c) {
        if (c < NCHUNK) {
            const int k0 = c * BK;
            const uint32_t base = sb + (c & 1) * STAGE_B;
            #pragma unroll
            for (int i = 0; i < 4; i++) {
                int id = tid + i * 256;
                int row = id >> 3, kc = id & 7;
                uint32_t soff = sw128((uint32_t)(row * 128 + kc * 16));
                const size_t gco = k0 + kc * 8;
                cp16(base + soff,              g_xh  + (size_t)(m0 + row) * K + gco);
                cp16(base + TILE_B + soff,     g_whi + (size_t)(n0 + row) * K + gco);
                cp16(base + 2 * TILE_B + soff, g_wlo + (size_t)(n0 + row) * K + gco);
            }
        }
        asm volatile("cp.async.commit_group;\n" ::: "memory");
    };

    issue(0);

    float acc[4][4][4];
    #pragma unroll
    for (int i = 0; i < 4; i++)
        #pragma unroll
        for (int j = 0; j < 4; j++)
            #pragma unroll
            for (int r = 0; r < 4; r++) acc[i][j][r] = 0.0f;

    #pragma unroll 1
    for (int c = 0; c < NCHUNK; c++) {
        asm volatile("cp.async.wait_group 0;\n" ::: "memory");
        __syncthreads();
        issue(c + 1);

        const uint32_t sA  = sb + (c & 1) * STAGE_B;
        const uint32_t sBh = sA + TILE_B;
        const uint32_t sBl = sA + 2 * TILE_B;

        #pragma unroll
        for (int ks = 0; ks < 4; ks++) {
            uint32_t a[4][4];
            #pragma unroll
            for (int mi = 0; mi < 4; mi++) {
                uint32_t off = sw128((uint32_t)((a_row + mi * 16) * 128 + ks * 32 + a_kb));
                ldm_x4(a[mi], sA + off);
            }
            #pragma unroll
            for (int bi = 0; bi < 2; bi++) {
                uint32_t off = sw128((uint32_t)((b_row + bi * 16) * 128 + ks * 32 + b_kb));
                uint32_t bh[4], bl[4];
                ldm_x4(bh, sBh + off);
                ldm_x4(bl, sBl + off);
                #pragma unroll
                for (int mi = 0; mi < 4; mi++) {
                    #pragma unroll
                    for (int njj = 0; njj < 2; njj++) {
                        const int nj = bi * 2 + njj, pr = njj * 2;
                        mma16816(acc[mi][nj], a[mi], bh[pr], bh[pr + 1]);
                        mma16816(acc[mi][nj], a[mi], bl[pr], bl[pr + 1]);
                    }
                }
            }
        }
        __syncthreads();
    }

    // epilogue: streaming stores (keep W/A hot in L2) — helped in R12
    const int r_base = m0 + wm + (lid >> 2);
    const int c_base = n0 + wn + (lid & 3) * 2;
    #pragma unroll
    for (int mi = 0; mi < 4; mi++) {
        #pragma unroll
        for (int nj = 0; nj < 4; nj++) {
            stg_cs_f2(&g_cur[(size_t)(r_base + mi * 16) * N + c_base + nj * 8],
                      make_float2(acc[mi][nj][0], acc[mi][nj][1]));
            stg_cs_f2(&g_cur[(size_t)(r_base + mi * 16 + 8) * N + c_base + nj * 8],
                      make_float2(acc[mi][nj][2], acc[mi][nj][3]));
        }
    }
}

// ---------------- LIF scan kernel (plain loads/stores — R10 version, roofline) ----------------
__global__ void scan_kernel(float* __restrict__ out) {
    const int id = blockIdx.x * blockDim.x + threadIdx.x;
    const int o = id & (N - 1);
    const int b = id >> 11;
    const float alpha_s = 0.8f;
    const float alpha_m = 0.95f;
    const float inv_tau = 0.05f;
    float V = 0.0f, I = 0.0f;
    #pragma unroll
    for (int t = 0; t < T; t++) {
        const size_t idx = ((size_t)(t * B + b)) * N + o;
        float cu = g_cur[idx];
        I = alpha_s * I + cu;
        V = alpha_m * V + inv_tau * I;
        float s = (V >= 1.0f) ? 1.0f : 0.0f;
        out[idx] = s;
        V = (V >= 1.0f) ? 0.0f : V;
    }
}

// ---------------- launch ----------------
extern "C" void kernel_launch(void* const* d_in, const int* in_sizes, int n_in,
                              void* d_out, int out_size) {
    const float* x = (const float*)d_in[0];       // [T, B, IN] fp32, binary
    const float* w = (const float*)d_in[1];       // [OUT, IN]  fp32
    float* out = (float*)d_out;                   // [T, B, OUT] fp32

    cudaFuncSetAttribute(gemm_kernel, cudaFuncAttributeMaxDynamicSharedMemorySize, SMEM_B);

    // conv_x first (streams 504MB with .cs), split_w last so W digits are L2-hot for GEMM
    conv_x_kernel<<<(int)(((size_t)M * K / 4 + 255) / 256), 256>>>(x);
    split_w_kernel<<<(N * K + 255) / 256, 256>>>(w);
    gemm_kernel<<<dim3(N / BN, M / BM), 256, SMEM_B>>>();
    scan_kernel<<<(B * N) / 256, 256>>>(out);
}